// round 13
// baseline (speedup 1.0000x reference)
#include <cuda_runtime.h>
#include <cuda_fp16.h>
#include <cuda_bf16.h>
#include <cstdint>

// ---------------------------------------------------------------------------
// MLP edge predictor (mma.sync bf16; tcgen05 unavailable at compute_103):
//   U = h @ W1[:256,:] + b1 ; V = h @ W1[256:,:]   (per node, fp16 in g_UV)
//   score_e = sigmoid( relu(U[src]+V[dst]) . W2 + b2 )
// Phase 0: transpose W1 -> bf16 K-major g_Bt [x][n][k]
// Phase A: bf16 m16n8k16 GEMM (exact R6 structure: staged epilogue in SM_B)
// Phase B: 2 edges/warp via 4-stage cp.async gather pipeline into smem,
//          half2 relu-add + fp32 dot + sigmoid
// ---------------------------------------------------------------------------

#define MAXN 100000

__device__ __half        g_UV[(size_t)MAXN * 512];
__device__ __nv_bfloat16 g_Bt[2 * 256 * 256];   // [x][n][k] bf16 (k contiguous)

__device__ __forceinline__ uint32_t smem_u32(const void* p) {
    uint32_t a;
    asm("{ .reg .u64 t; cvta.to.shared.u64 t, %1; cvt.u32.u64 %0, t; }" : "=r"(a) : "l"(p));
    return a;
}
__device__ __forceinline__ void ldsm4(uint32_t* r, uint32_t a) {
    asm volatile("ldmatrix.sync.aligned.m8n8.x4.shared.b16 {%0,%1,%2,%3}, [%4];"
                 : "=r"(r[0]), "=r"(r[1]), "=r"(r[2]), "=r"(r[3]) : "r"(a));
}
__device__ __forceinline__ void mma_bf16(float* c, const uint32_t* a,
                                         uint32_t b0, uint32_t b1) {
    asm volatile(
        "mma.sync.aligned.m16n8k16.row.col.f32.bf16.bf16.f32 "
        "{%0,%1,%2,%3}, {%4,%5,%6,%7}, {%8,%9}, {%0,%1,%2,%3};"
        : "+f"(c[0]), "+f"(c[1]), "+f"(c[2]), "+f"(c[3])
        : "r"(a[0]), "r"(a[1]), "r"(a[2]), "r"(a[3]), "r"(b0), "r"(b1));
}
__device__ __forceinline__ void lds128(uint4& v, uint32_t a) {
    asm volatile("ld.shared.v4.u32 {%0,%1,%2,%3}, [%4];"
                 : "=r"(v.x), "=r"(v.y), "=r"(v.z), "=r"(v.w) : "r"(a));
}
#define CP_ASYNC16(dst, src) \
    asm volatile("cp.async.cg.shared.global [%0], [%1], 16;" :: "r"(dst), "l"(src))
#define CP_COMMIT() asm volatile("cp.async.commit_group;")
#define CP_WAIT0()  asm volatile("cp.async.wait_group 0;" ::: "memory")

// GEMM smem layout: A 64KB | B 128KB | bias 1KB
#define SM_A    0
#define SM_B    65536
#define SM_BIAS (65536 + 131072)
#define SM_TOT  (65536 + 131072 + 1024)

// ------------------- W1 transpose prep -------------------
__global__ void prep_w1(const float* __restrict__ W1) {
    __shared__ float t[32][33];
    int x = blockIdx.z, k0 = blockIdx.y * 32, n0 = blockIdx.x * 32;
    int tx = threadIdx.x, ty = threadIdx.y;   // 32 x 8
    #pragma unroll
    for (int i = 0; i < 4; i++) {
        int k = k0 + ty + i * 8;
        t[ty + i * 8][tx] = W1[(size_t)(x * 256 + k) * 256 + n0 + tx];
    }
    __syncthreads();
    #pragma unroll
    for (int i = 0; i < 4; i++) {
        int n = n0 + ty + i * 8;
        g_Bt[x * 65536 + n * 256 + k0 + tx] = __float2bfloat16(t[tx][ty + i * 8]);
    }
}

// ------------------- GEMM: one CTA = 128 rows x 512 cols (R6) -------------
__global__ void __launch_bounds__(512, 1) gemm_uv_kernel(
    const float* __restrict__ h, const float* __restrict__ b1, int M)
{
    extern __shared__ char smem[];
    const uint32_t sbase = smem_u32(smem);
    const int tid  = threadIdx.x;
    const int lane = tid & 31;
    const int warp = tid >> 5;          // 0..15
    const int wm   = warp >> 2;         // 0..3  -> m offset 32*wm
    const int wn   = warp & 3;          // 0..3  -> n offset 64*wn
    const int mBase = blockIdx.x * 128;
    float* biasS = (float*)(smem + SM_BIAS);

    if (tid < 256) biasS[tid] = b1[tid];

    // ---- issue B fill for x=0 via cp.async (overlaps the A fill below) ----
    #pragma unroll
    for (int it = 0; it < 16; it++) {
        int g = tid + it * 512;         // 0..8191
        int n = g >> 5;
        int j = g & 31;
        uint32_t dst = sbase + SM_B + n * 512 + ((j ^ (n & 7)) << 4);
        CP_ASYNC16(dst, g_Bt + n * 256 + j * 8);
    }
    CP_COMMIT();

    // ---- A fill: h -> bf16, swizzled ----
    #pragma unroll
    for (int it = 0; it < 8; it++) {
        int g   = tid + it * 512;       // 0..4095
        int row = g >> 5;
        int j   = g & 31;
        float4 v0 = make_float4(0.f, 0.f, 0.f, 0.f), v1 = v0;
        if (mBase + row < M) {
            const float* p = h + (size_t)(mBase + row) * 256 + j * 8;
            v0 = *(const float4*)p;
            v1 = *(const float4*)(p + 4);
        }
        __nv_bfloat162 p0 = __floats2bfloat162_rn(v0.x, v0.y);
        __nv_bfloat162 p1 = __floats2bfloat162_rn(v0.z, v0.w);
        __nv_bfloat162 p2 = __floats2bfloat162_rn(v1.x, v1.y);
        __nv_bfloat162 p3 = __floats2bfloat162_rn(v1.z, v1.w);
        uint4 pk;
        pk.x = *(uint32_t*)&p0; pk.y = *(uint32_t*)&p1;
        pk.z = *(uint32_t*)&p2; pk.w = *(uint32_t*)&p3;
        *(uint4*)(smem + SM_A + row * 512 + ((j ^ (row & 7)) << 4)) = pk;
    }
    CP_WAIT0();
    __syncthreads();

    for (int x = 0; x < 2; x++) {
        // ---- mainloop: 16 K-steps, warp tile 32x64 ----
        float acc[2][8][4];
        #pragma unroll
        for (int i = 0; i < 2; i++)
            #pragma unroll
            for (int jj = 0; jj < 8; jj++)
                #pragma unroll
                for (int k = 0; k < 4; k++) acc[i][jj][k] = 0.f;

        #pragma unroll 4
        for (int ks = 0; ks < 16; ks++) {
            uint32_t af[2][4];
            #pragma unroll
            for (int mt = 0; mt < 2; mt++) {
                int row = wm * 32 + mt * 16 + (lane & 15);
                int j   = ks * 2 + (lane >> 4);
                ldsm4(af[mt], sbase + SM_A + row * 512 + ((j ^ (row & 7)) << 4));
            }
            uint32_t bf[4][4];
            #pragma unroll
            for (int p = 0; p < 4; p++) {
                int n = wn * 64 + p * 16 + (lane & 7) + ((lane >> 4) << 3);
                int j = ks * 2 + ((lane >> 3) & 1);
                ldsm4(bf[p], sbase + SM_B + n * 512 + ((j ^ (n & 7)) << 4));
            }
            #pragma unroll
            for (int mt = 0; mt < 2; mt++)
                #pragma unroll
                for (int nt = 0; nt < 8; nt++)
                    mma_bf16(acc[mt][nt], af[mt],
                             bf[nt >> 1][(nt & 1) * 2], bf[nt >> 1][(nt & 1) * 2 + 1]);
        }
        __syncthreads();   // B reads done before staging reuses SM_B

        // ---- stage acc -> SM_B (128 rows x 256 half, swizzled) ----
        #pragma unroll
        for (int mt = 0; mt < 2; mt++) {
            #pragma unroll
            for (int nt = 0; nt < 8; nt++) {
                int n = wn * 64 + nt * 8 + 2 * (lane & 3);
                float bv0 = (x == 0) ? biasS[n]     : 0.f;
                float bv1 = (x == 0) ? biasS[n + 1] : 0.f;
                int m0 = wm * 32 + mt * 16 + (lane >> 2);
                uint32_t byo = (uint32_t)(n * 2);
                uint32_t lo0 = (((byo >> 4) ^ (m0 & 7)) << 4) + (byo & 15);
                __half2 hA = __floats2half2_rn(acc[mt][nt][0] + bv0,
                                               acc[mt][nt][1] + bv1);
                *(__half2*)(smem + SM_B + m0 * 512 + lo0) = hA;
                int m1 = m0 + 8;
                uint32_t lo1 = (((byo >> 4) ^ (m1 & 7)) << 4) + (byo & 15);
                __half2 hB = __floats2half2_rn(acc[mt][nt][2] + bv0,
                                               acc[mt][nt][3] + bv1);
                *(__half2*)(smem + SM_B + m1 * 512 + lo1) = hB;
            }
        }
        __syncthreads();

        // ---- coalesced 16B stores to g_UV ----
        #pragma unroll
        for (int it = 0; it < 8; it++) {
            int g   = tid + it * 512;   // 0..4095
            int row = g >> 5;
            int j   = g & 31;
            uint4 v = *(uint4*)(smem + SM_B + row * 512 + ((j ^ (row & 7)) << 4));
            if (mBase + row < M)
                *(uint4*)(g_UV + (size_t)(mBase + row) * 512 + x * 256 + j * 8) = v;
        }
        __syncthreads();   // SM_B free

        // ---- refill B for x=1 ----
        if (x == 0) {
            #pragma unroll
            for (int it = 0; it < 16; it++) {
                int g = tid + it * 512;
                int n = g >> 5;
                int j = g & 31;
                uint32_t dst = sbase + SM_B + n * 512 + ((j ^ (n & 7)) << 4);
                CP_ASYNC16(dst, g_Bt + 65536 + n * 256 + j * 8);
            }
            CP_COMMIT();
            CP_WAIT0();
            __syncthreads();
        }
    }
}

// ------------------- edge scoring: cp.async gather pipeline ---------------
// 2 edges/warp-iter; 4-stage ring, 2KB/stage/warp, 64KB/block (8 warps).
#define ES_S 4

__global__ void __launch_bounds__(256) edge_score_kernel(
    const int* __restrict__ src, const int* __restrict__ dst,
    const float* __restrict__ W2, const float* __restrict__ b2,
    float* __restrict__ out, int E)
{
    extern __shared__ char esm[];
    const int lane = threadIdx.x & 31;
    const int wIn  = threadIdx.x >> 5;
    const int j    = lane & 15;
    const int half = lane >> 4;
    const int gw   = blockIdx.x * 8 + wIn;
    const int nW   = gridDim.x * 8;
    const int nP   = (E + 1) >> 1;

    const uint32_t sb = smem_u32(esm) + wIn * (ES_S * 2048);

    float4 wl0 = __ldg((const float4*)(W2 + j * 8));
    float4 wl1 = __ldg((const float4*)(W2 + j * 8 + 4));
    float4 wh0 = __ldg((const float4*)(W2 + 128 + j * 8));
    float4 wh1 = __ldg((const float4*)(W2 + 128 + j * 8 + 4));
    const float wlo[8] = {wl0.x, wl0.y, wl0.z, wl0.w, wl1.x, wl1.y, wl1.z, wl1.w};
    const float whi[8] = {wh0.x, wh0.y, wh0.z, wh0.w, wh1.x, wh1.y, wh1.z, wh1.w};
    const float bb = __ldg(b2);
    const __half2 z2 = __float2half2_rn(0.f);

    // prologue: fill ES_S stages
    #pragma unroll
    for (int s = 0; s < ES_S; s++) {
        int p = gw + s * nW;
        if (p < nP) {
            int e = p * 2 + half;
            if (e > E - 1) e = E - 1;
            int si = __ldg(src + e);
            int di = __ldg(dst + e);
            const char* ub = (const char*)g_UV + (size_t)si * 1024 + j * 16;
            const char* vb = (const char*)g_UV + (size_t)di * 1024 + 512 + j * 16;
            uint32_t du = sb + s * 2048 + half * 1024 + j * 16;
            CP_ASYNC16(du,       ub);
            CP_ASYNC16(du + 256, ub + 256);
            CP_ASYNC16(du + 512, vb);
            CP_ASYNC16(du + 768, vb + 256);
        }
        CP_COMMIT();
    }

    int st = 0;
    for (int p = gw; p < nP; p += nW) {
        asm volatile("cp.async.wait_group %0;" :: "n"(ES_S - 1) : "memory");

        const uint32_t a = sb + st * 2048 + half * 1024 + j * 16;
        uint4 u0, u1, v0, v1;
        lds128(u0, a);
        lds128(u1, a + 256);
        lds128(v0, a + 512);
        lds128(v1, a + 768);

        const __half2* uh0 = (const __half2*)&u0;
        const __half2* vh0 = (const __half2*)&v0;
        const __half2* uh1 = (const __half2*)&u1;
        const __half2* vh1 = (const __half2*)&v1;

        float acc = 0.f;
        #pragma unroll
        for (int i = 0; i < 4; i++) {
            __half2 t0 = __hmax2(__hadd2(uh0[i], vh0[i]), z2);
            float2 f0 = __half22float2(t0);
            acc = fmaf(f0.x, wlo[2 * i],     acc);
            acc = fmaf(f0.y, wlo[2 * i + 1], acc);
            __half2 t1 = __hmax2(__hadd2(uh1[i], vh1[i]), z2);
            float2 f1 = __half22float2(t1);
            acc = fmaf(f1.x, whi[2 * i],     acc);
            acc = fmaf(f1.y, whi[2 * i + 1], acc);
        }
        #pragma unroll
        for (int o = 8; o > 0; o >>= 1)
            acc += __shfl_xor_sync(0xffffffffu, acc, o);

        int e = p * 2 + half;
        if (j == 0 && e < E)
            out[e] = 1.0f / (1.0f + __expf(-(acc + bb)));

        // refill this stage ES_S iterations ahead
        int pn = p + ES_S * nW;
        if (pn < nP) {
            int en = pn * 2 + half;
            if (en > E - 1) en = E - 1;
            int si = __ldg(src + en);
            int di = __ldg(dst + en);
            const char* ub = (const char*)g_UV + (size_t)si * 1024 + j * 16;
            const char* vb = (const char*)g_UV + (size_t)di * 1024 + 512 + j * 16;
            uint32_t du = sb + st * 2048 + half * 1024 + j * 16;
            CP_ASYNC16(du,       ub);
            CP_ASYNC16(du + 256, ub + 256);
            CP_ASYNC16(du + 512, vb);
            CP_ASYNC16(du + 768, vb + 256);
        }
        CP_COMMIT();
        st = (st + 1) & (ES_S - 1);
    }
}

extern "C" void kernel_launch(void* const* d_in, const int* in_sizes, int n_in,
                              void* d_out, int out_size)
{
    const float* h   = (const float*)d_in[0];
    const int*   src = (const int*)d_in[1];
    const int*   dst = (const int*)d_in[2];
    const float* W1  = (const float*)d_in[3];
    const float* b1  = (const float*)d_in[4];
    const float* W2  = (const float*)d_in[5];
    const float* b2  = (const float*)d_in[6];
    float* out = (float*)d_out;

    int M = in_sizes[0] / 256;
    int E = in_sizes[1];

    cudaFuncSetAttribute(gemm_uv_kernel,
                         cudaFuncAttributeMaxDynamicSharedMemorySize, SM_TOT);
    cudaFuncSetAttribute(edge_score_kernel,
                         cudaFuncAttributeMaxDynamicSharedMemorySize, 8 * ES_S * 2048);

    prep_w1<<<dim3(8, 8, 2), dim3(32, 8)>>>(W1);
    gemm_uv_kernel<<<(M + 127) / 128, 512, SM_TOT>>>(h, b1, M);
    edge_score_kernel<<<444, 256, 8 * ES_S * 2048>>>(src, dst, W2, b2, out, E);
}

// round 14
// speedup vs baseline: 1.0957x; 1.0957x over previous
#include <cuda_runtime.h>
#include <cuda_fp16.h>
#include <cuda_bf16.h>
#include <cstdint>

// ---------------------------------------------------------------------------
// MLP edge predictor (mma.sync bf16; tcgen05 unavailable at compute_103):
//   U = h @ W1[:256,:] + b1 ; V = h @ W1[256:,:]   (per node, fp16 in g_UV)
//   score_e = sigmoid( relu(U[src]+V[dst]) . W2 + b2 )
// Phase 0: transpose W1 -> bf16 K-major g_Bt [x][n][k]
// Phase A: bf16 m16n8k16 GEMM (R6 structure: staged epilogue in SM_B)
// Phase B: 2 edges/warp gather + half2 relu-add + fp32 dot + sigmoid,
//          grid-stride with unroll 4
// ---------------------------------------------------------------------------

#define MAXN 100000

__device__ __half        g_UV[(size_t)MAXN * 512];
__device__ __nv_bfloat16 g_Bt[2 * 256 * 256];   // [x][n][k] bf16 (k contiguous)

__device__ __forceinline__ uint32_t smem_u32(const void* p) {
    uint32_t a;
    asm("{ .reg .u64 t; cvta.to.shared.u64 t, %1; cvt.u32.u64 %0, t; }" : "=r"(a) : "l"(p));
    return a;
}
__device__ __forceinline__ void ldsm4(uint32_t* r, uint32_t a) {
    asm volatile("ldmatrix.sync.aligned.m8n8.x4.shared.b16 {%0,%1,%2,%3}, [%4];"
                 : "=r"(r[0]), "=r"(r[1]), "=r"(r[2]), "=r"(r[3]) : "r"(a));
}
__device__ __forceinline__ void mma_bf16(float* c, const uint32_t* a,
                                         uint32_t b0, uint32_t b1) {
    asm volatile(
        "mma.sync.aligned.m16n8k16.row.col.f32.bf16.bf16.f32 "
        "{%0,%1,%2,%3}, {%4,%5,%6,%7}, {%8,%9}, {%0,%1,%2,%3};"
        : "+f"(c[0]), "+f"(c[1]), "+f"(c[2]), "+f"(c[3])
        : "r"(a[0]), "r"(a[1]), "r"(a[2]), "r"(a[3]), "r"(b0), "r"(b1));
}
#define CP_ASYNC16(dst, src) \
    asm volatile("cp.async.cg.shared.global [%0], [%1], 16;" :: "r"(dst), "l"(src))
#define CP_COMMIT() asm volatile("cp.async.commit_group;")
#define CP_WAIT0()  asm volatile("cp.async.wait_group 0;" ::: "memory")

// smem layout (dynamic): A 64KB | B 128KB | bias 1KB
#define SM_A    0
#define SM_B    65536
#define SM_BIAS (65536 + 131072)
#define SM_TOT  (65536 + 131072 + 1024)

// ------------------- W1 transpose prep -------------------
__global__ void prep_w1(const float* __restrict__ W1) {
    __shared__ float t[32][33];
    int x = blockIdx.z, k0 = blockIdx.y * 32, n0 = blockIdx.x * 32;
    int tx = threadIdx.x, ty = threadIdx.y;   // 32 x 8
    #pragma unroll
    for (int i = 0; i < 4; i++) {
        int k = k0 + ty + i * 8;
        t[ty + i * 8][tx] = W1[(size_t)(x * 256 + k) * 256 + n0 + tx];
    }
    __syncthreads();
    #pragma unroll
    for (int i = 0; i < 4; i++) {
        int n = n0 + ty + i * 8;
        g_Bt[x * 65536 + n * 256 + k0 + tx] = __float2bfloat16(t[tx][ty + i * 8]);
    }
}

// ------------------- GEMM: one CTA = 128 rows x 512 cols -------------------
__global__ void __launch_bounds__(512, 1) gemm_uv_kernel(
    const float* __restrict__ h, const float* __restrict__ b1, int M)
{
    extern __shared__ char smem[];
    const uint32_t sbase = smem_u32(smem);
    const int tid  = threadIdx.x;
    const int lane = tid & 31;
    const int warp = tid >> 5;          // 0..15
    const int wm   = warp >> 2;         // 0..3  -> m offset 32*wm
    const int wn   = warp & 3;          // 0..3  -> n offset 64*wn
    const int mBase = blockIdx.x * 128;
    float* biasS = (float*)(smem + SM_BIAS);

    if (tid < 256) biasS[tid] = b1[tid];

    // ---- issue B fill for x=0 via cp.async (overlaps the A fill below) ----
    #pragma unroll
    for (int it = 0; it < 16; it++) {
        int g = tid + it * 512;         // 0..8191
        int n = g >> 5;
        int j = g & 31;
        uint32_t dst = sbase + SM_B + n * 512 + ((j ^ (n & 7)) << 4);
        CP_ASYNC16(dst, g_Bt + n * 256 + j * 8);
    }
    CP_COMMIT();

    // ---- A fill: h -> bf16, swizzled ----
    #pragma unroll
    for (int it = 0; it < 8; it++) {
        int g   = tid + it * 512;       // 0..4095
        int row = g >> 5;
        int j   = g & 31;
        float4 v0 = make_float4(0.f, 0.f, 0.f, 0.f), v1 = v0;
        if (mBase + row < M) {
            const float* p = h + (size_t)(mBase + row) * 256 + j * 8;
            v0 = *(const float4*)p;
            v1 = *(const float4*)(p + 4);
        }
        __nv_bfloat162 p0 = __floats2bfloat162_rn(v0.x, v0.y);
        __nv_bfloat162 p1 = __floats2bfloat162_rn(v0.z, v0.w);
        __nv_bfloat162 p2 = __floats2bfloat162_rn(v1.x, v1.y);
        __nv_bfloat162 p3 = __floats2bfloat162_rn(v1.z, v1.w);
        uint4 pk;
        pk.x = *(uint32_t*)&p0; pk.y = *(uint32_t*)&p1;
        pk.z = *(uint32_t*)&p2; pk.w = *(uint32_t*)&p3;
        *(uint4*)(smem + SM_A + row * 512 + ((j ^ (row & 7)) << 4)) = pk;
    }
    CP_WAIT0();
    __syncthreads();

    for (int x = 0; x < 2; x++) {
        // ---- mainloop: 16 K-steps, warp tile 32x64 ----
        float acc[2][8][4];
        #pragma unroll
        for (int i = 0; i < 2; i++)
            #pragma unroll
            for (int jj = 0; jj < 8; jj++)
                #pragma unroll
                for (int k = 0; k < 4; k++) acc[i][jj][k] = 0.f;

        #pragma unroll 4
        for (int ks = 0; ks < 16; ks++) {
            uint32_t af[2][4];
            #pragma unroll
            for (int mt = 0; mt < 2; mt++) {
                int row = wm * 32 + mt * 16 + (lane & 15);
                int j   = ks * 2 + (lane >> 4);
                ldsm4(af[mt], sbase + SM_A + row * 512 + ((j ^ (row & 7)) << 4));
            }
            uint32_t bf[4][4];
            #pragma unroll
            for (int p = 0; p < 4; p++) {
                int n = wn * 64 + p * 16 + (lane & 7) + ((lane >> 4) << 3);
                int j = ks * 2 + ((lane >> 3) & 1);
                ldsm4(bf[p], sbase + SM_B + n * 512 + ((j ^ (n & 7)) << 4));
            }
            #pragma unroll
            for (int mt = 0; mt < 2; mt++)
                #pragma unroll
                for (int nt = 0; nt < 8; nt++)
                    mma_bf16(acc[mt][nt], af[mt],
                             bf[nt >> 1][(nt & 1) * 2], bf[nt >> 1][(nt & 1) * 2 + 1]);
        }
        __syncthreads();   // B reads done before staging reuses SM_B

        // ---- stage acc -> SM_B (128 rows x 256 half, swizzled) ----
        #pragma unroll
        for (int mt = 0; mt < 2; mt++) {
            #pragma unroll
            for (int nt = 0; nt < 8; nt++) {
                int n = wn * 64 + nt * 8 + 2 * (lane & 3);
                float bv0 = (x == 0) ? biasS[n]     : 0.f;
                float bv1 = (x == 0) ? biasS[n + 1] : 0.f;
                int m0 = wm * 32 + mt * 16 + (lane >> 2);
                uint32_t byo = (uint32_t)(n * 2);
                uint32_t lo0 = (((byo >> 4) ^ (m0 & 7)) << 4) + (byo & 15);
                __half2 hA = __floats2half2_rn(acc[mt][nt][0] + bv0,
                                               acc[mt][nt][1] + bv1);
                *(__half2*)(smem + SM_B + m0 * 512 + lo0) = hA;
                int m1 = m0 + 8;
                uint32_t lo1 = (((byo >> 4) ^ (m1 & 7)) << 4) + (byo & 15);
                __half2 hB = __floats2half2_rn(acc[mt][nt][2] + bv0,
                                               acc[mt][nt][3] + bv1);
                *(__half2*)(smem + SM_B + m1 * 512 + lo1) = hB;
            }
        }
        __syncthreads();

        // ---- coalesced 16B stores to g_UV ----
        #pragma unroll
        for (int it = 0; it < 8; it++) {
            int g   = tid + it * 512;   // 0..4095
            int row = g >> 5;
            int j   = g & 31;
            uint4 v = *(uint4*)(smem + SM_B + row * 512 + ((j ^ (row & 7)) << 4));
            if (mBase + row < M)
                *(uint4*)(g_UV + (size_t)(mBase + row) * 512 + x * 256 + j * 8) = v;
        }
        __syncthreads();   // SM_B free

        // ---- refill B for x=1 ----
        if (x == 0) {
            #pragma unroll
            for (int it = 0; it < 16; it++) {
                int g = tid + it * 512;
                int n = g >> 5;
                int j = g & 31;
                uint32_t dst = sbase + SM_B + n * 512 + ((j ^ (n & 7)) << 4);
                CP_ASYNC16(dst, g_Bt + 65536 + n * 256 + j * 8);
            }
            CP_COMMIT();
            CP_WAIT0();
            __syncthreads();
        }
    }
}

// ------------------- edge scoring: 2 edges per warp, unroll 4 -------------
__global__ void __launch_bounds__(256) edge_score_kernel(
    const int* __restrict__ src, const int* __restrict__ dst,
    const float* __restrict__ W2, const float* __restrict__ b2,
    float* __restrict__ out, int E)
{
    const int lane = threadIdx.x & 31;
    const int j    = lane & 15;
    const int half = lane >> 4;
    const int gw   = (blockIdx.x * blockDim.x + threadIdx.x) >> 5;
    const int nW   = (gridDim.x * blockDim.x) >> 5;

    float4 wl0 = __ldg((const float4*)(W2 + j * 8));
    float4 wl1 = __ldg((const float4*)(W2 + j * 8 + 4));
    float4 wh0 = __ldg((const float4*)(W2 + 128 + j * 8));
    float4 wh1 = __ldg((const float4*)(W2 + 128 + j * 8 + 4));
    const float wlo[8] = {wl0.x, wl0.y, wl0.z, wl0.w, wl1.x, wl1.y, wl1.z, wl1.w};
    const float whi[8] = {wh0.x, wh0.y, wh0.z, wh0.w, wh1.x, wh1.y, wh1.z, wh1.w};
    const float bb = __ldg(b2);
    const __half2 z2 = __float2half2_rn(0.f);

    #pragma unroll 4
    for (int e = gw * 2 + half; e < E; e += nW * 2) {
        int s = __ldg(src + e);
        int d = __ldg(dst + e);
        const uint4* up = (const uint4*)(g_UV + (size_t)s * 512);
        const uint4* vp = (const uint4*)(g_UV + (size_t)d * 512 + 256);
        uint4 u0 = __ldg(up + j),  u1 = __ldg(up + j + 16);
        uint4 v0 = __ldg(vp + j),  v1 = __ldg(vp + j + 16);

        const __half2* uh0 = (const __half2*)&u0;
        const __half2* vh0 = (const __half2*)&v0;
        const __half2* uh1 = (const __half2*)&u1;
        const __half2* vh1 = (const __half2*)&v1;

        float acc = 0.f;
        #pragma unroll
        for (int i = 0; i < 4; i++) {
            __half2 t0 = __hmax2(__hadd2(uh0[i], vh0[i]), z2);
            float2 f0 = __half22float2(t0);
            acc = fmaf(f0.x, wlo[2 * i],     acc);
            acc = fmaf(f0.y, wlo[2 * i + 1], acc);
            __half2 t1 = __hmax2(__hadd2(uh1[i], vh1[i]), z2);
            float2 f1 = __half22float2(t1);
            acc = fmaf(f1.x, whi[2 * i],     acc);
            acc = fmaf(f1.y, whi[2 * i + 1], acc);
        }
        #pragma unroll
        for (int o = 8; o > 0; o >>= 1)
            acc += __shfl_xor_sync(0xffffffffu, acc, o);
        if (j == 0)
            out[e] = 1.0f / (1.0f + __expf(-(acc + bb)));
    }
}

extern "C" void kernel_launch(void* const* d_in, const int* in_sizes, int n_in,
                              void* d_out, int out_size)
{
    const float* h   = (const float*)d_in[0];
    const int*   src = (const int*)d_in[1];
    const int*   dst = (const int*)d_in[2];
    const float* W1  = (const float*)d_in[3];
    const float* b1  = (const float*)d_in[4];
    const float* W2  = (const float*)d_in[5];
    const float* b2  = (const float*)d_in[6];
    float* out = (float*)d_out;

    int M = in_sizes[0] / 256;
    int E = in_sizes[1];

    cudaFuncSetAttribute(gemm_uv_kernel,
                         cudaFuncAttributeMaxDynamicSharedMemorySize, SM_TOT);

    prep_w1<<<dim3(8, 8, 2), dim3(32, 8)>>>(W1);
    gemm_uv_kernel<<<(M + 127) / 128, 512, SM_TOT>>>(h, b1, M);
    edge_score_kernel<<<1184, 256>>>(src, dst, W2, b2, out, E);
}